// round 16
// baseline (speedup 1.0000x reference)
#include <cuda_runtime.h>
#include <cuda_bf16.h>
#include <stdint.h>
#include <math.h>

// Problem constants
constexpr int Bb = 32;
constexpr int Ss = 512;
constexpr int DM = 256;     // d_model = H*d_k
constexpr int NH = 16;
constexpr int DH = 16;
constexpr int Mrows = Bb * Ss;  // 16384

// Single consolidated scratch: 6 sections of Mrows*DM bf16 each.
// order: qh ql kh kl vh vl. q pre-scaled by 0.25*log2(e).
constexpr size_t SEC = (size_t)Mrows * DM;
__device__ __nv_bfloat16 g_all[6 * SEC];
constexpr int SQH = 0, SQL = 1, SKH = 2, SKL = 3, SVH = 4, SVL = 5;
// Pre-split weights (3 x 256 x 256)
__device__ __nv_bfloat16 g_wh[3 * DM * DM], g_wl[3 * DM * DM];

__device__ __forceinline__ uint32_t smem_u32(const void* p) {
    uint32_t a;
    asm("{ .reg .u64 t; cvta.to.shared.u64 t, %1; cvt.u32.u64 %0, t; }" : "=r"(a) : "l"(p));
    return a;
}

__device__ __forceinline__ uint32_t pack_bf16x2(float a, float b) {
    uint32_t r;
    asm("cvt.rn.bf16x2.f32 %0, %1, %2;" : "=r"(r) : "f"(b), "f"(a));
    return r;
}

__device__ __forceinline__ uint32_t bfsplit_pack(float a, float b, uint32_t& lopack) {
    uint32_t hi = pack_bf16x2(a, b);
    float ar = a - __uint_as_float(hi << 16);
    float br = b - __uint_as_float(hi & 0xFFFF0000u);
    lopack = pack_bf16x2(ar, br);
    return hi;
}

__device__ __forceinline__ float ex2f(float x) {
    float r;
    asm("ex2.approx.f32 %0, %1;" : "=f"(r) : "f"(x));
    return r;
}
__device__ __forceinline__ float lg2f(float x) {
    float r;
    asm("lg2.approx.f32 %0, %1;" : "=f"(r) : "f"(x));
    return r;
}

__device__ __forceinline__ void mma_bf16(float c[4], const uint32_t a[4],
                                         uint32_t b0, uint32_t b1) {
    asm volatile(
        "mma.sync.aligned.m16n8k16.row.col.f32.bf16.bf16.f32 "
        "{%0,%1,%2,%3}, {%4,%5,%6,%7}, {%8,%9}, {%0,%1,%2,%3};\n"
        : "+f"(c[0]), "+f"(c[1]), "+f"(c[2]), "+f"(c[3])
        : "r"(a[0]), "r"(a[1]), "r"(a[2]), "r"(a[3]), "r"(b0), "r"(b1));
}

__device__ __forceinline__ void ldm_x4(uint32_t r[4], uint32_t addr) {
    asm volatile("ldmatrix.sync.aligned.m8n8.x4.shared.b16 {%0,%1,%2,%3}, [%4];"
                 : "=r"(r[0]), "=r"(r[1]), "=r"(r[2]), "=r"(r[3]) : "r"(addr));
}
__device__ __forceinline__ void ldm_x4_t(uint32_t r[4], uint32_t addr) {
    asm volatile("ldmatrix.sync.aligned.m8n8.x4.trans.shared.b16 {%0,%1,%2,%3}, [%4];"
                 : "=r"(r[0]), "=r"(r[1]), "=r"(r[2]), "=r"(r[3]) : "r"(addr));
}

// ===========================================================================
// One-shot weight split: W (fp32) -> g_wh/g_wl (bf16)
// ===========================================================================
__global__ __launch_bounds__(256) void w_split(
    const float* __restrict__ WQ, const float* __restrict__ WK, const float* __restrict__ WV)
{
    const int i = blockIdx.x * 256 + threadIdx.x;   // [0, 65536)
    const float* src[3] = {WQ, WK, WV};
    #pragma unroll
    for (int z = 0; z < 3; z++) {
        const float w = src[z][i];
        const __nv_bfloat16 wh = __float2bfloat16(w);
        g_wh[z * DM * DM + i] = wh;
        g_wl[z * DM * DM + i] = __float2bfloat16(w - __bfloat162float(wh));
    }
}

// ===========================================================================
// Projection GEMM v3: CTA = 64M x 128N, 8 warps of 32M x 32N (acc = 32 regs)
// for 3 CTAs/SM (24 warps/SM, +50% vs R11's 16). W pre-split (uint4 copies);
// A converted in loader. split-bf16 3-term MMAs. Q output pre-scaled.
// ===========================================================================
constexpr int RW = 20;  // u32 per 32-bf16 row (80 B)
constexpr float QSCALE = 0.3606737602222409f;  // 0.25 * log2(e)

__global__ __launch_bounds__(256, 3) void proj_mma(
    const float* __restrict__ Qin, const float* __restrict__ Kin, const float* __restrict__ Vin,
    const float* __restrict__ bQ,  const float* __restrict__ bK,  const float* __restrict__ bV)
{
    __shared__ __align__(16) uint32_t Ah[64 * RW], Al[64 * RW];     // 5 KB each
    __shared__ __align__(16) uint32_t Wh[128 * RW], Wl[128 * RW];   // 10 KB each

    const float* A; const float* bias; float scale;
    __nv_bfloat16 *Ch, *Cl;
    if (blockIdx.z == 0)      { A = Qin; bias = bQ; Ch = g_all + SQH * SEC; Cl = g_all + SQL * SEC; scale = QSCALE; }
    else if (blockIdx.z == 1) { A = Kin; bias = bK; Ch = g_all + SKH * SEC; Cl = g_all + SKL * SEC; scale = 1.0f; }
    else                      { A = Vin; bias = bV; Ch = g_all + SVH * SEC; Cl = g_all + SVL * SEC; scale = 1.0f; }
    const uint32_t* wbh = reinterpret_cast<const uint32_t*>(g_wh) + blockIdx.z * (DM * DM / 2);
    const uint32_t* wbl = reinterpret_cast<const uint32_t*>(g_wl) + blockIdx.z * (DM * DM / 2);

    const int tid = threadIdx.x;
    const int wid = tid >> 5, lane = tid & 31;
    const int warpM = wid >> 2, warpN = wid & 3;    // 2 x 4 warp grid
    const int row0 = blockIdx.y * 64;
    const int col0 = blockIdx.x * 128;

    const uint32_t okA = (uint32_t)(warpM * 32 + (lane & 15)) * 80 + ((lane >> 4) << 4);
    const uint32_t okB = (uint32_t)(warpN * 32 + (lane & 7) + ((lane >> 4) << 3)) * 80
                       + (((lane >> 3) & 1) << 4);
    const uint32_t sAh = smem_u32(Ah) + okA, sAl = smem_u32(Al) + okA;
    const uint32_t sWh = smem_u32(Wh) + okB, sWl = smem_u32(Wl) + okB;

    // A loader: 4 threads/row, 8 floats each. W loader: 2 threads/row, 8 u32 each.
    const int lrA = tid >> 2, sgA = (tid & 3) * 8;
    const int lrW = tid >> 1, sgW = (tid & 1) * 8;

    float acc[2][4][4];
    #pragma unroll
    for (int m = 0; m < 2; m++)
        #pragma unroll
        for (int nt = 0; nt < 4; nt++)
            #pragma unroll
            for (int j = 0; j < 4; j++) acc[m][nt][j] = 0.0f;

    for (int it = 0; it < 8; it++) {
        if (it) __syncthreads();
        {
            // --- A chunk [64 x 32] fp32 -> split bf16 ---
            const float* srcA = A + (size_t)(row0 + lrA) * DM + it * 32 + sgA;
            float4 f0 = *reinterpret_cast<const float4*>(srcA);
            float4 f1 = *reinterpret_cast<const float4*>(srcA + 4);
            uint4 h0, l0;
            h0.x = bfsplit_pack(f0.x, f0.y, l0.x); h0.y = bfsplit_pack(f0.z, f0.w, l0.y);
            h0.z = bfsplit_pack(f1.x, f1.y, l0.z); h0.w = bfsplit_pack(f1.z, f1.w, l0.w);
            const int soA = lrA * RW + sgA / 2;
            *reinterpret_cast<uint4*>(&Ah[soA]) = h0;
            *reinterpret_cast<uint4*>(&Al[soA]) = l0;

            // --- W chunk [128 x 32] pre-split bf16, pure copies ---
            const uint32_t woff = (uint32_t)(col0 + lrW) * (DM / 2) + (uint32_t)(it * 16 + sgW);
            const int soW = lrW * RW + sgW;
            *reinterpret_cast<uint4*>(&Wh[soW])     = *reinterpret_cast<const uint4*>(wbh + woff);
            *reinterpret_cast<uint4*>(&Wh[soW + 4]) = *reinterpret_cast<const uint4*>(wbh + woff + 4);
            *reinterpret_cast<uint4*>(&Wl[soW])     = *reinterpret_cast<const uint4*>(wbl + woff);
            *reinterpret_cast<uint4*>(&Wl[soW + 4]) = *reinterpret_cast<const uint4*>(wbl + woff + 4);
        }
        __syncthreads();

        #pragma unroll
        for (int ks = 0; ks < 2; ks++) {
            uint32_t aah[2][4], aal[2][4];
            ldm_x4(aah[0], sAh + ks * 32);
            ldm_x4(aal[0], sAl + ks * 32);
            ldm_x4(aah[1], sAh + 16 * 80 + ks * 32);
            ldm_x4(aal[1], sAl + 16 * 80 + ks * 32);

            #pragma unroll
            for (int np = 0; np < 2; np++) {
                uint32_t bh[4], bl[4];
                ldm_x4(bh, sWh + np * 16 * 80 + ks * 32);
                ldm_x4(bl, sWl + np * 16 * 80 + ks * 32);
                #pragma unroll
                for (int m = 0; m < 2; m++) {
                    mma_bf16(acc[m][2 * np],     aah[m], bh[0], bh[1]);
                    mma_bf16(acc[m][2 * np],     aal[m], bh[0], bh[1]);
                    mma_bf16(acc[m][2 * np],     aah[m], bl[0], bl[1]);
                    mma_bf16(acc[m][2 * np + 1], aah[m], bh[2], bh[3]);
                    mma_bf16(acc[m][2 * np + 1], aal[m], bh[2], bh[3]);
                    mma_bf16(acc[m][2 * np + 1], aah[m], bl[2], bl[3]);
                }
            }
        }
    }

    const int tq = lane & 3, g8 = lane >> 2;
    #pragma unroll
    for (int m = 0; m < 2; m++) {
        const size_t r0 = (size_t)(row0 + warpM * 32 + m * 16 + g8);
        #pragma unroll
        for (int nt = 0; nt < 4; nt++) {
            const int c = col0 + warpN * 32 + nt * 8 + 2 * tq;
            const float b0 = bias[c], b1 = bias[c + 1];
            uint32_t lo0, lo1;
            uint32_t hi0 = bfsplit_pack((acc[m][nt][0] + b0) * scale, (acc[m][nt][1] + b1) * scale, lo0);
            uint32_t hi1 = bfsplit_pack((acc[m][nt][2] + b0) * scale, (acc[m][nt][3] + b1) * scale, lo1);
            *reinterpret_cast<uint32_t*>(Ch + r0 * DM + c) = hi0;
            *reinterpret_cast<uint32_t*>(Cl + r0 * DM + c) = lo0;
            *reinterpret_cast<uint32_t*>(Ch + (r0 + 8) * DM + c) = hi1;
            *reinterpret_cast<uint32_t*>(Cl + (r0 + 8) * DM + c) = lo1;
        }
    }
}

// ===========================================================================
// Attention: EXACT R11 body (best measured: 92.6us).
// ===========================================================================
constexpr int ROWU = 12;   // u32 stride per 16-bf16 row (48 B)

__global__ __launch_bounds__(128, 5) void attn_mma(const float* __restrict__ mask,
                                                   float* __restrict__ out)
{
    __shared__ __align__(16) uint32_t Qh[128 * ROWU], Ql[128 * ROWU];
    __shared__ __align__(16) uint32_t Kh[128 * ROWU], Kl[128 * ROWU];
    __shared__ __align__(16) uint32_t Vh[128 * ROWU], Vl[128 * ROWU];
    __shared__ float ms[128];   // log2(mask)

    const int tid = threadIdx.x;
    const int wid = tid >> 5, lane = tid & 31;
    const int t = lane & 3;
    const int q0 = blockIdx.x * 128;
    const int h = blockIdx.y;
    const int b = blockIdx.z;

    const uint32_t* gall = reinterpret_cast<const uint32_t*>(g_all);
    constexpr size_t SECU = SEC / 2;

    const uint32_t okk = ((lane & 7) + ((lane >> 4) << 3)) * 48 + (((lane >> 3) & 1) << 4);
    const uint32_t okv = ((lane & 7) + (((lane >> 3) & 1) << 3)) * 48 + ((lane >> 4) << 4);
    const uint32_t okq0 = (wid * 32 + (lane & 7) + (((lane >> 3) & 1) << 3)) * 48 + ((lane >> 4) << 4);

    const uint32_t sKh = smem_u32(Kh) + okk, sKl = smem_u32(Kl) + okk;
    const uint32_t sVh = smem_u32(Vh) + okv, sVl = smem_u32(Vl) + okv;

    #pragma unroll
    for (int i = tid; i < 512; i += 128) {
        const int r = i >> 2, u = (i & 3) * 2;
        const size_t gi = ((size_t)(b * Ss + q0 + r)) * 128 + h * 8 + u;
        *reinterpret_cast<uint2*>(&Qh[r * ROWU + u]) = *reinterpret_cast<const uint2*>(gall + SQH * SECU + gi);
        *reinterpret_cast<uint2*>(&Ql[r * ROWU + u]) = *reinterpret_cast<const uint2*>(gall + SQL * SECU + gi);
    }
    __syncthreads();

    uint32_t qah[2][4], qal[2][4];
    ldm_x4(qah[0], smem_u32(Qh) + okq0);
    ldm_x4(qal[0], smem_u32(Ql) + okq0);
    ldm_x4(qah[1], smem_u32(Qh) + okq0 + 16 * 48);
    ldm_x4(qal[1], smem_u32(Ql) + okq0 + 16 * 48);

    float ctx[2][2][4];
    float den[2][2];
    #pragma unroll
    for (int m = 0; m < 2; m++) {
        den[m][0] = den[m][1] = 0.0f;
        #pragma unroll
        for (int nn = 0; nn < 2; nn++)
            #pragma unroll
            for (int j = 0; j < 4; j++) ctx[m][nn][j] = 0.0f;
    }

    for (int c = 0; c < 4; c++) {
        __syncthreads();

        #pragma unroll
        for (int i = tid; i < 512; i += 128) {
            const int r = i >> 2, u = (i & 3) * 2;
            const size_t gi = ((size_t)(b * Ss + c * 128 + r)) * 128 + h * 8 + u;
            *reinterpret_cast<uint2*>(&Kh[r * ROWU + u]) = *reinterpret_cast<const uint2*>(gall + SKH * SECU + gi);
            *reinterpret_cast<uint2*>(&Kl[r * ROWU + u]) = *reinterpret_cast<const uint2*>(gall + SKL * SECU + gi);
            *reinterpret_cast<uint2*>(&Vh[r * ROWU + u]) = *reinterpret_cast<const uint2*>(gall + SVH * SECU + gi);
            *reinterpret_cast<uint2*>(&Vl[r * ROWU + u]) = *reinterpret_cast<const uint2*>(gall + SVL * SECU + gi);
        }
        ms[tid] = lg2f(mask[b * Ss + c * 128 + tid]);
        __syncthreads();

        #pragma unroll
        for (int kt = 0; kt < 8; kt++) {
            uint32_t bh[4], bl[4];
            ldm_x4(bh, sKh + kt * 768);
            ldm_x4(bl, sKl + kt * 768);

            const float m0 = ms[kt * 16 + 2 * t];
            const float m1 = ms[kt * 16 + 2 * t + 1];
            const float m2 = ms[kt * 16 + 8 + 2 * t];
            const float m3 = ms[kt * 16 + 8 + 2 * t + 1];

            float sc[2][2][4];
            #pragma unroll
            for (int m = 0; m < 2; m++) {
                sc[m][0][0] = m0; sc[m][0][1] = m1; sc[m][0][2] = m0; sc[m][0][3] = m1;
                sc[m][1][0] = m2; sc[m][1][1] = m3; sc[m][1][2] = m2; sc[m][1][3] = m3;
                mma_bf16(sc[m][0], qah[m], bh[0], bh[1]);
                mma_bf16(sc[m][0], qah[m], bl[0], bl[1]);
                mma_bf16(sc[m][0], qal[m], bh[0], bh[1]);
                mma_bf16(sc[m][1], qah[m], bh[2], bh[3]);
                mma_bf16(sc[m][1], qah[m], bl[2], bl[3]);
                mma_bf16(sc[m][1], qal[m], bh[2], bh[3]);
            }

            uint32_t vh[4], vl[4];
            ldm_x4_t(vh, sVh + kt * 768);
            ldm_x4_t(vl, sVl + kt * 768);

            #pragma unroll
            for (int m = 0; m < 2; m++) {
                const float p00 = ex2f(sc[m][0][0]);
                const float p01 = ex2f(sc[m][0][1]);
                const float p02 = ex2f(sc[m][0][2]);
                const float p03 = ex2f(sc[m][0][3]);
                const float p10 = ex2f(sc[m][1][0]);
                const float p11 = ex2f(sc[m][1][1]);
                const float p12 = ex2f(sc[m][1][2]);
                const float p13 = ex2f(sc[m][1][3]);
                den[m][0] += p00 + p01 + p10 + p11;
                den[m][1] += p02 + p03 + p12 + p13;

                uint32_t pah[4], pal[4];
                pah[0] = bfsplit_pack(p00, p01, pal[0]);
                pah[1] = bfsplit_pack(p02, p03, pal[1]);
                pah[2] = bfsplit_pack(p10, p11, pal[2]);
                pah[3] = bfsplit_pack(p12, p13, pal[3]);

                mma_bf16(ctx[m][0], pah, vh[0], vh[1]);
                mma_bf16(ctx[m][0], pah, vl[0], vl[1]);
                mma_bf16(ctx[m][0], pal, vh[0], vh[1]);
                mma_bf16(ctx[m][1], pah, vh[2], vh[3]);
                mma_bf16(ctx[m][1], pah, vl[2], vl[3]);
                mma_bf16(ctx[m][1], pal, vh[2], vh[3]);
            }
        }
    }

    const int g = lane >> 2;
    #pragma unroll
    for (int m = 0; m < 2; m++) {
        float d0 = den[m][0], d1 = den[m][1];
        d0 += __shfl_xor_sync(0xFFFFFFFFu, d0, 1);
        d0 += __shfl_xor_sync(0xFFFFFFFFu, d0, 2);
        d1 += __shfl_xor_sync(0xFFFFFFFFu, d1, 1);
        d1 += __shfl_xor_sync(0xFFFFFFFFu, d1, 2);
        const float i0 = 1.0f / (d0 + 1e-8f);
        const float i1 = 1.0f / (d1 + 1e-8f);

        const size_t row0 = (size_t)(b * Ss + q0 + wid * 32 + m * 16 + g);
        float2 o00 = make_float2(ctx[m][0][0] * i0, ctx[m][0][1] * i0);
        float2 o01 = make_float2(ctx[m][0][2] * i1, ctx[m][0][3] * i1);
        float2 o10 = make_float2(ctx[m][1][0] * i0, ctx[m][1][1] * i0);
        float2 o11 = make_float2(ctx[m][1][2] * i1, ctx[m][1][3] * i1);
        *reinterpret_cast<float2*>(out + row0 * DM + h * DH + 2 * t) = o00;
        *reinterpret_cast<float2*>(out + (row0 + 8) * DM + h * DH + 2 * t) = o01;
        *reinterpret_cast<float2*>(out + row0 * DM + h * DH + 8 + 2 * t) = o10;
        *reinterpret_cast<float2*>(out + (row0 + 8) * DM + h * DH + 8 + 2 * t) = o11;
    }
}

// ===========================================================================
extern "C" void kernel_launch(void* const* d_in, const int* in_sizes, int n_in,
                              void* d_out, int out_size)
{
    const float* Q    = (const float*)d_in[0];
    const float* K    = (const float*)d_in[1];
    const float* V    = (const float*)d_in[2];
    const float* mask = (const float*)d_in[3];
    const float* W_Q  = (const float*)d_in[4];
    const float* b_Q  = (const float*)d_in[5];
    const float* W_K  = (const float*)d_in[6];
    const float* b_K  = (const float*)d_in[7];
    const float* W_V  = (const float*)d_in[8];
    const float* b_V  = (const float*)d_in[9];
    float* out = (float*)d_out;

    w_split<<<DM * DM / 256, 256>>>(W_Q, W_K, W_V);

    dim3 gridP(2, Mrows / 64, 3);   // (N-tile 128, M-tile 64, projection)
    proj_mma<<<gridP, 256>>>(Q, K, V, b_Q, b_K, b_V);

    dim3 gridA(4, NH, Bb);
    attn_mma<<<gridA, 128>>>(mask, out);
}

// round 17
// speedup vs baseline: 1.0871x; 1.0871x over previous
#include <cuda_runtime.h>
#include <cuda_bf16.h>
#include <stdint.h>
#include <math.h>

// Problem constants
constexpr int Bb = 32;
constexpr int Ss = 512;
constexpr int DM = 256;     // d_model = H*d_k
constexpr int NH = 16;
constexpr int DH = 16;
constexpr int Mrows = Bb * Ss;  // 16384

// Single consolidated scratch: 6 sections of Mrows*DM bf16 each.
// order: qh ql kh kl vh vl. q pre-scaled by 0.25*log2(e).
constexpr size_t SEC = (size_t)Mrows * DM;
__device__ __nv_bfloat16 g_all[6 * SEC];
constexpr int SQH = 0, SQL = 1, SKH = 2, SKL = 3, SVH = 4, SVL = 5;

__device__ __forceinline__ uint32_t smem_u32(const void* p) {
    uint32_t a;
    asm("{ .reg .u64 t; cvta.to.shared.u64 t, %1; cvt.u32.u64 %0, t; }" : "=r"(a) : "l"(p));
    return a;
}

__device__ __forceinline__ uint32_t pack_bf16x2(float a, float b) {
    uint32_t r;
    asm("cvt.rn.bf16x2.f32 %0, %1, %2;" : "=r"(r) : "f"(b), "f"(a));
    return r;
}

__device__ __forceinline__ uint32_t bfsplit_pack(float a, float b, uint32_t& lopack) {
    uint32_t hi = pack_bf16x2(a, b);
    float ar = a - __uint_as_float(hi << 16);
    float br = b - __uint_as_float(hi & 0xFFFF0000u);
    lopack = pack_bf16x2(ar, br);
    return hi;
}

__device__ __forceinline__ float ex2f(float x) {
    float r;
    asm("ex2.approx.f32 %0, %1;" : "=f"(r) : "f"(x));
    return r;
}
__device__ __forceinline__ float lg2f(float x) {
    float r;
    asm("lg2.approx.f32 %0, %1;" : "=f"(r) : "f"(x));
    return r;
}

__device__ __forceinline__ void mma_bf16(float c[4], const uint32_t a[4],
                                         uint32_t b0, uint32_t b1) {
    asm volatile(
        "mma.sync.aligned.m16n8k16.row.col.f32.bf16.bf16.f32 "
        "{%0,%1,%2,%3}, {%4,%5,%6,%7}, {%8,%9}, {%0,%1,%2,%3};\n"
        : "+f"(c[0]), "+f"(c[1]), "+f"(c[2]), "+f"(c[3])
        : "r"(a[0]), "r"(a[1]), "r"(a[2]), "r"(a[3]), "r"(b0), "r"(b1));
}

__device__ __forceinline__ void ldm_x4(uint32_t r[4], uint32_t addr) {
    asm volatile("ldmatrix.sync.aligned.m8n8.x4.shared.b16 {%0,%1,%2,%3}, [%4];"
                 : "=r"(r[0]), "=r"(r[1]), "=r"(r[2]), "=r"(r[3]) : "r"(addr));
}
__device__ __forceinline__ void ldm_x4_t(uint32_t r[4], uint32_t addr) {
    asm volatile("ldmatrix.sync.aligned.m8n8.x4.trans.shared.b16 {%0,%1,%2,%3}, [%4];"
                 : "=r"(r[0]), "=r"(r[1]), "=r"(r[2]), "=r"(r[3]) : "r"(addr));
}

// ===========================================================================
// Projection GEMM via mma.sync, split-bf16 (hh + lh + hl).
// EXACT R11 body (proj local optimum: ~79us; R16 proved smaller tiles regress)
// ===========================================================================
constexpr int RW = 20;  // u32 per 32-bf16 row (80 B)
constexpr float QSCALE = 0.3606737602222409f;  // 0.25 * log2(e)

__global__ __launch_bounds__(256, 2) void proj_mma(
    const float* __restrict__ Qin, const float* __restrict__ Kin, const float* __restrict__ Vin,
    const float* __restrict__ WQ,  const float* __restrict__ WK,  const float* __restrict__ WV,
    const float* __restrict__ bQ,  const float* __restrict__ bK,  const float* __restrict__ bV)
{
    __shared__ __align__(16) uint32_t Ah[128 * RW], Al[128 * RW];
    __shared__ __align__(16) uint32_t Wh[128 * RW], Wl[128 * RW];

    const float* A; const float* W; const float* bias; float scale;
    __nv_bfloat16 *Ch, *Cl;
    if (blockIdx.z == 0)      { A = Qin; W = WQ; bias = bQ; Ch = g_all + SQH * SEC; Cl = g_all + SQL * SEC; scale = QSCALE; }
    else if (blockIdx.z == 1) { A = Kin; W = WK; bias = bK; Ch = g_all + SKH * SEC; Cl = g_all + SKL * SEC; scale = 1.0f; }
    else                      { A = Vin; W = WV; bias = bV; Ch = g_all + SVH * SEC; Cl = g_all + SVL * SEC; scale = 1.0f; }

    const int tid = threadIdx.x;
    const int wid = tid >> 5, lane = tid & 31;
    const int warpM = wid >> 1, warpN = wid & 1;
    const int row0 = blockIdx.y * 128;
    const int col0 = blockIdx.x * 128;

    const uint32_t okA = (uint32_t)(warpM * 32 + (lane & 15)) * 80 + ((lane >> 4) << 4);
    const uint32_t okB = (uint32_t)(warpN * 64 + (lane & 7) + ((lane >> 4) << 3)) * 80
                       + (((lane >> 3) & 1) << 4);
    const uint32_t sAh = smem_u32(Ah) + okA, sAl = smem_u32(Al) + okA;
    const uint32_t sWh = smem_u32(Wh) + okB, sWl = smem_u32(Wl) + okB;

    const int lr = tid >> 1, sg = (tid & 1) * 16;

    float acc[2][8][4];
    #pragma unroll
    for (int m = 0; m < 2; m++)
        #pragma unroll
        for (int nt = 0; nt < 8; nt++)
            #pragma unroll
            for (int j = 0; j < 4; j++) acc[m][nt][j] = 0.0f;

    for (int it = 0; it < 8; it++) {
        if (it) __syncthreads();
        {
            const float* srcA = A + (size_t)(row0 + lr) * DM + it * 32 + sg;
            const float* srcW = W + (size_t)(col0 + lr) * DM + it * 32 + sg;
            uint4 h0, h1, l0, l1;
            float4 f0 = *reinterpret_cast<const float4*>(srcA);
            float4 f1 = *reinterpret_cast<const float4*>(srcA + 4);
            float4 f2 = *reinterpret_cast<const float4*>(srcA + 8);
            float4 f3 = *reinterpret_cast<const float4*>(srcA + 12);
            h0.x = bfsplit_pack(f0.x, f0.y, l0.x); h0.y = bfsplit_pack(f0.z, f0.w, l0.y);
            h0.z = bfsplit_pack(f1.x, f1.y, l0.z); h0.w = bfsplit_pack(f1.z, f1.w, l0.w);
            h1.x = bfsplit_pack(f2.x, f2.y, l1.x); h1.y = bfsplit_pack(f2.z, f2.w, l1.y);
            h1.z = bfsplit_pack(f3.x, f3.y, l1.z); h1.w = bfsplit_pack(f3.z, f3.w, l1.w);
            const int so = lr * RW + sg / 2;
            *reinterpret_cast<uint4*>(&Ah[so]) = h0; *reinterpret_cast<uint4*>(&Ah[so + 4]) = h1;
            *reinterpret_cast<uint4*>(&Al[so]) = l0; *reinterpret_cast<uint4*>(&Al[so + 4]) = l1;

            f0 = *reinterpret_cast<const float4*>(srcW);
            f1 = *reinterpret_cast<const float4*>(srcW + 4);
            f2 = *reinterpret_cast<const float4*>(srcW + 8);
            f3 = *reinterpret_cast<const float4*>(srcW + 12);
            h0.x = bfsplit_pack(f0.x, f0.y, l0.x); h0.y = bfsplit_pack(f0.z, f0.w, l0.y);
            h0.z = bfsplit_pack(f1.x, f1.y, l0.z); h0.w = bfsplit_pack(f1.z, f1.w, l0.w);
            h1.x = bfsplit_pack(f2.x, f2.y, l1.x); h1.y = bfsplit_pack(f2.z, f2.w, l1.y);
            h1.z = bfsplit_pack(f3.x, f3.y, l1.z); h1.w = bfsplit_pack(f3.z, f3.w, l1.w);
            *reinterpret_cast<uint4*>(&Wh[so]) = h0; *reinterpret_cast<uint4*>(&Wh[so + 4]) = h1;
            *reinterpret_cast<uint4*>(&Wl[so]) = l0; *reinterpret_cast<uint4*>(&Wl[so + 4]) = l1;
        }
        __syncthreads();

        #pragma unroll
        for (int ks = 0; ks < 2; ks++) {
            uint32_t aah[2][4], aal[2][4];
            ldm_x4(aah[0], sAh + ks * 32);
            ldm_x4(aal[0], sAl + ks * 32);
            ldm_x4(aah[1], sAh + 16 * 80 + ks * 32);
            ldm_x4(aal[1], sAl + 16 * 80 + ks * 32);

            #pragma unroll
            for (int np = 0; np < 4; np++) {
                uint32_t bh[4], bl[4];
                ldm_x4(bh, sWh + np * 16 * 80 + ks * 32);
                ldm_x4(bl, sWl + np * 16 * 80 + ks * 32);
                #pragma unroll
                for (int m = 0; m < 2; m++) {
                    mma_bf16(acc[m][2 * np],     aah[m], bh[0], bh[1]);
                    mma_bf16(acc[m][2 * np],     aal[m], bh[0], bh[1]);
                    mma_bf16(acc[m][2 * np],     aah[m], bl[0], bl[1]);
                    mma_bf16(acc[m][2 * np + 1], aah[m], bh[2], bh[3]);
                    mma_bf16(acc[m][2 * np + 1], aal[m], bh[2], bh[3]);
                    mma_bf16(acc[m][2 * np + 1], aah[m], bl[2], bl[3]);
                }
            }
        }
    }

    const int tq = lane & 3, g8 = lane >> 2;
    #pragma unroll
    for (int m = 0; m < 2; m++) {
        const size_t r0 = (size_t)(row0 + warpM * 32 + m * 16 + g8);
        #pragma unroll
        for (int nt = 0; nt < 8; nt++) {
            const int c = col0 + warpN * 64 + nt * 8 + 2 * tq;
            const float b0 = bias[c], b1 = bias[c + 1];
            uint32_t lo0, lo1;
            uint32_t hi0 = bfsplit_pack((acc[m][nt][0] + b0) * scale, (acc[m][nt][1] + b1) * scale, lo0);
            uint32_t hi1 = bfsplit_pack((acc[m][nt][2] + b0) * scale, (acc[m][nt][3] + b1) * scale, lo1);
            *reinterpret_cast<uint32_t*>(Ch + r0 * DM + c) = hi0;
            *reinterpret_cast<uint32_t*>(Cl + r0 * DM + c) = lo0;
            *reinterpret_cast<uint32_t*>(Ch + (r0 + 8) * DM + c) = hi1;
            *reinterpret_cast<uint32_t*>(Cl + (r0 + 8) * DM + c) = lo1;
        }
    }
}

// ===========================================================================
// Attention v5: 256 threads / 8 warps, q-tile = 256 rows; each warp keeps the
// R11-proven 32-row workload (m=2). K/V chunks loaded ONCE per 256 q-rows
// (halves loader work + chip K/V traffic). Mask stowed in Kh row padding.
// Smem = exactly 48 KB -> 3 CTAs/SM at <=85 regs (R12 precedent: 80 regs).
// ===========================================================================
constexpr int ROWU = 12;   // u32 stride per 16-bf16 row (48 B); K pad col 8 = lg2(mask)

__global__ __launch_bounds__(256, 3) void attn_mma(const float* __restrict__ mask,
                                                   float* __restrict__ out)
{
    __shared__ __align__(16) uint32_t Qh[256 * ROWU], Ql[256 * ROWU];  // 12 KB each
    __shared__ __align__(16) uint32_t Kh[128 * ROWU], Kl[128 * ROWU];  // 6 KB each
    __shared__ __align__(16) uint32_t Vh[128 * ROWU], Vl[128 * ROWU];  // 6 KB each

    const int tid = threadIdx.x;
    const int wid = tid >> 5, lane = tid & 31;
    const int t = lane & 3;
    const int q0 = blockIdx.x * 256;
    const int h = blockIdx.y;
    const int b = blockIdx.z;

    const uint32_t* gall = reinterpret_cast<const uint32_t*>(g_all);
    constexpr size_t SECU = SEC / 2;

    const uint32_t okk = ((lane & 7) + ((lane >> 4) << 3)) * 48 + (((lane >> 3) & 1) << 4);
    const uint32_t okv = ((lane & 7) + (((lane >> 3) & 1) << 3)) * 48 + ((lane >> 4) << 4);
    const uint32_t okq0 = (wid * 32 + (lane & 7) + (((lane >> 3) & 1) << 3)) * 48 + ((lane >> 4) << 4);

    const uint32_t sKh = smem_u32(Kh) + okk, sKl = smem_u32(Kl) + okk;
    const uint32_t sVh = smem_u32(Vh) + okv, sVl = smem_u32(Vl) + okv;

    // load Q tile [256 x 16] hi/lo (4 iters of uint2, 4 threads/row)
    #pragma unroll
    for (int i = tid; i < 1024; i += 256) {
        const int r = i >> 2, u = (i & 3) * 2;
        const size_t gi = ((size_t)(b * Ss + q0 + r)) * 128 + h * 8 + u;
        *reinterpret_cast<uint2*>(&Qh[r * ROWU + u]) = *reinterpret_cast<const uint2*>(gall + SQH * SECU + gi);
        *reinterpret_cast<uint2*>(&Ql[r * ROWU + u]) = *reinterpret_cast<const uint2*>(gall + SQL * SECU + gi);
    }
    __syncthreads();

    uint32_t qah[2][4], qal[2][4];
    ldm_x4(qah[0], smem_u32(Qh) + okq0);
    ldm_x4(qal[0], smem_u32(Ql) + okq0);
    ldm_x4(qah[1], smem_u32(Qh) + okq0 + 16 * 48);
    ldm_x4(qal[1], smem_u32(Ql) + okq0 + 16 * 48);

    float ctx[2][2][4];
    float den[2][2];
    #pragma unroll
    for (int m = 0; m < 2; m++) {
        den[m][0] = den[m][1] = 0.0f;
        #pragma unroll
        for (int nn = 0; nn < 2; nn++)
            #pragma unroll
            for (int j = 0; j < 4; j++) ctx[m][nn][j] = 0.0f;
    }

    for (int c = 0; c < 4; c++) {
        __syncthreads();   // prev chunk reads done (Q load sync covers c=0)

        // K/V chunk loader: 2 iters of uint2 per array (256 threads, 128 rows)
        #pragma unroll
        for (int i = tid; i < 512; i += 256) {
            const int r = i >> 2, u = (i & 3) * 2;
            const size_t gi = ((size_t)(b * Ss + c * 128 + r)) * 128 + h * 8 + u;
            *reinterpret_cast<uint2*>(&Kh[r * ROWU + u]) = *reinterpret_cast<const uint2*>(gall + SKH * SECU + gi);
            *reinterpret_cast<uint2*>(&Kl[r * ROWU + u]) = *reinterpret_cast<const uint2*>(gall + SKL * SECU + gi);
            *reinterpret_cast<uint2*>(&Vh[r * ROWU + u]) = *reinterpret_cast<const uint2*>(gall + SVH * SECU + gi);
            *reinterpret_cast<uint2*>(&Vl[r * ROWU + u]) = *reinterpret_cast<const uint2*>(gall + SVL * SECU + gi);
        }
        if (tid < 128)
            Kh[tid * ROWU + 8] = __float_as_uint(lg2f(mask[b * Ss + c * 128 + tid]));
        __syncthreads();

        #pragma unroll
        for (int kt = 0; kt < 8; kt++) {
            uint32_t bh[4], bl[4];
            ldm_x4(bh, sKh + kt * 768);
            ldm_x4(bl, sKl + kt * 768);

            const float m0 = __uint_as_float(Kh[(kt * 16 + 2 * t) * ROWU + 8]);
            const float m1 = __uint_as_float(Kh[(kt * 16 + 2 * t + 1) * ROWU + 8]);
            const float m2 = __uint_as_float(Kh[(kt * 16 + 8 + 2 * t) * ROWU + 8]);
            const float m3 = __uint_as_float(Kh[(kt * 16 + 8 + 2 * t + 1) * ROWU + 8]);

            float sc[2][2][4];
            #pragma unroll
            for (int m = 0; m < 2; m++) {
                sc[m][0][0] = m0; sc[m][0][1] = m1; sc[m][0][2] = m0; sc[m][0][3] = m1;
                sc[m][1][0] = m2; sc[m][1][1] = m3; sc[m][1][2] = m2; sc[m][1][3] = m3;
                mma_bf16(sc[m][0], qah[m], bh[0], bh[1]);
                mma_bf16(sc[m][0], qah[m], bl[0], bl[1]);
                mma_bf16(sc[m][0], qal[m], bh[0], bh[1]);
                mma_bf16(sc[m][1], qah[m], bh[2], bh[3]);
                mma_bf16(sc[m][1], qah[m], bl[2], bl[3]);
                mma_bf16(sc[m][1], qal[m], bh[2], bh[3]);
            }

            uint32_t vh[4], vl[4];
            ldm_x4_t(vh, sVh + kt * 768);
            ldm_x4_t(vl, sVl + kt * 768);

            #pragma unroll
            for (int m = 0; m < 2; m++) {
                const float p00 = ex2f(sc[m][0][0]);
                const float p01 = ex2f(sc[m][0][1]);
                const float p02 = ex2f(sc[m][0][2]);
                const float p03 = ex2f(sc[m][0][3]);
                const float p10 = ex2f(sc[m][1][0]);
                const float p11 = ex2f(sc[m][1][1]);
                const float p12 = ex2f(sc[m][1][2]);
                const float p13 = ex2f(sc[m][1][3]);
                den[m][0] += p00 + p01 + p10 + p11;
                den[m][1] += p02 + p03 + p12 + p13;

                uint32_t pah[4], pal[4];
                pah[0] = bfsplit_pack(p00, p01, pal[0]);
                pah[1] = bfsplit_pack(p02, p03, pal[1]);
                pah[2] = bfsplit_pack(p10, p11, pal[2]);
                pah[3] = bfsplit_pack(p12, p13, pal[3]);

                mma_bf16(ctx[m][0], pah, vh[0], vh[1]);
                mma_bf16(ctx[m][0], pah, vl[0], vl[1]);
                mma_bf16(ctx[m][0], pal, vh[0], vh[1]);
                mma_bf16(ctx[m][1], pah, vh[2], vh[3]);
                mma_bf16(ctx[m][1], pah, vl[2], vl[3]);
                mma_bf16(ctx[m][1], pal, vh[2], vh[3]);
            }
        }
    }

    const int g = lane >> 2;
    #pragma unroll
    for (int m = 0; m < 2; m++) {
        float d0 = den[m][0], d1 = den[m][1];
        d0 += __shfl_xor_sync(0xFFFFFFFFu, d0, 1);
        d0 += __shfl_xor_sync(0xFFFFFFFFu, d0, 2);
        d1 += __shfl_xor_sync(0xFFFFFFFFu, d1, 1);
        d1 += __shfl_xor_sync(0xFFFFFFFFu, d1, 2);
        const float i0 = 1.0f / (d0 + 1e-8f);
        const float i1 = 1.0f / (d1 + 1e-8f);

        const size_t row0 = (size_t)(b * Ss + q0 + wid * 32 + m * 16 + g);
        float2 o00 = make_float2(ctx[m][0][0] * i0, ctx[m][0][1] * i0);
        float2 o01 = make_float2(ctx[m][0][2] * i1, ctx[m][0][3] * i1);
        float2 o10 = make_float2(ctx[m][1][0] * i0, ctx[m][1][1] * i0);
        float2 o11 = make_float2(ctx[m][1][2] * i1, ctx[m][1][3] * i1);
        *reinterpret_cast<float2*>(out + row0 * DM + h * DH + 2 * t) = o00;
        *reinterpret_cast<float2*>(out + (row0 + 8) * DM + h * DH + 2 * t) = o01;
        *reinterpret_cast<float2*>(out + row0 * DM + h * DH + 8 + 2 * t) = o10;
        *reinterpret_cast<float2*>(out + (row0 + 8) * DM + h * DH + 8 + 2 * t) = o11;
    }
}

// ===========================================================================
extern "C" void kernel_launch(void* const* d_in, const int* in_sizes, int n_in,
                              void* d_out, int out_size)
{
    const float* Q    = (const float*)d_in[0];
    const float* K    = (const float*)d_in[1];
    const float* V    = (const float*)d_in[2];
    const float* mask = (const float*)d_in[3];
    const float* W_Q  = (const float*)d_in[4];
    const float* b_Q  = (const float*)d_in[5];
    const float* W_K  = (const float*)d_in[6];
    const float* b_K  = (const float*)d_in[7];
    const float* W_V  = (const float*)d_in[8];
    const float* b_V  = (const float*)d_in[9];
    float* out = (float*)d_out;

    dim3 gridP(2, Mrows / 128, 3);
    proj_mma<<<gridP, 256>>>(Q, K, V, W_Q, W_K, W_V, b_Q, b_K, b_V);

    dim3 gridA(2, NH, Bb);   // q-tile 256 -> 1024 CTAs
    attn_mma<<<gridA, 256>>>(mask, out);
}